// round 9
// baseline (speedup 1.0000x reference)
#include <cuda_runtime.h>
#include <cstdint>
#include <math.h>

#define S_LEN 512
#define BATCH 256
#define IN    256
#define HID   1024
#define SWID  256
#define SDEP  100
#define KTOT  1536
#define IS    (IN + SWID)     // 512
#define NB    128
#define NT    512

#define BUFSZ  2112           // A frag buffer: 4 mt * 4 ks * 132
#define BBASE  (2 * BUFSZ)    // float offset of B ring in dyn smem
#define DYNSM  ((2 * BUFSZ + 4 * 4096) * 4)   // 82432 bytes

// ---------------- scratch (no allocations allowed) ----------------
__device__ __align__(16) float g_stackA[BATCH * SDEP * SWID];   // 26.2 MB
__device__ __align__(16) float g_stackB[BATCH * SDEP * SWID];   // 26.2 MB (also prep staging)
__device__ __align__(16) float g_Wf[32 * 48 * 4096];            // 25.2 MB tile-ordered weights
__device__ __align__(16) float g_bias[4 * HID];
__device__ __align__(16) float g_c[BATCH * HID];
__device__ __align__(16) float g_d[2 * BATCH * SWID];
__device__ float g_ctl[2 * BATCH * 3];
__device__ unsigned g_cnt;
__device__ volatile unsigned g_gen;

// ---------------- helpers ----------------
__device__ __forceinline__ float ftf32(float x) {
    float y;
    asm("cvt.rna.tf32.f32 %0, %1;" : "=f"(y) : "f"(x));
    return y;
}
__device__ __forceinline__ uint32_t smem_u32(const void* p) {
    uint32_t a;
    asm("{ .reg .u64 t; cvta.to.shared.u64 t, %1; cvt.u32.u64 %0, t; }" : "=r"(a) : "l"(p));
    return a;
}
__device__ __forceinline__ void cpa16(uint32_t dst, const void* src) {
    asm volatile("cp.async.cg.shared.global [%0], [%1], 16;" :: "r"(dst), "l"(src) : "memory");
}
__device__ __forceinline__ void cpa_commit() { asm volatile("cp.async.commit_group;" ::: "memory"); }
template <int N> __device__ __forceinline__ void cpa_wait() {
    asm volatile("cp.async.wait_group %0;" :: "n"(N) : "memory");
}

__device__ __forceinline__ void mma_tf32(float c[4], const uint32_t a[4], const uint32_t b[2]) {
    asm volatile(
        "mma.sync.aligned.m16n8k8.row.col.f32.tf32.tf32.f32 "
        "{%0,%1,%2,%3}, {%4,%5,%6,%7}, {%8,%9}, {%0,%1,%2,%3};\n"
        : "+f"(c[0]), "+f"(c[1]), "+f"(c[2]), "+f"(c[3])
        : "r"(a[0]), "r"(a[1]), "r"(a[2]), "r"(a[3]), "r"(b[0]), "r"(b[1]));
}

// ---------------- software grid barrier ----------------
__device__ __forceinline__ void bar_arrive(unsigned* myGen) {
    __syncthreads();
    if (threadIdx.x == 0) {
        unsigned my = g_gen;
        __threadfence();
        unsigned a = atomicAdd(&g_cnt, 1u);
        if (a == NB - 1) {
            g_cnt = 0;
            __threadfence();
            g_gen = my + 1;
        }
        *myGen = my;
    }
}
__device__ __forceinline__ void bar_wait(unsigned myGen) {
    if (threadIdx.x == 0) {
        while (g_gen == myGen) { }
        __threadfence();
    }
    __syncthreads();
}
__device__ __forceinline__ void gbar() {
    unsigned m;
    bar_arrive(&m);
    bar_wait(m);
}

// ---------------- stack blend ----------------
__device__ __forceinline__ void blend_range(
    const float* __restrict__ Sp, float* __restrict__ So,
    const float* __restrict__ dbuf, const float* __restrict__ ctlbuf,
    int is_t0, int bid, int tid)
{
    const float4* sin4  = (const float4*)Sp;
    float4*       sout4 = (float4*)So;
    const float4* d4    = (const float4*)dbuf;
    const int per_blk = (BATCH * SDEP * (SWID / 4)) / NB;   // 12800
    for (int ii = tid; ii < per_blk; ii += NT) {
        const int idx = bid * per_blk + ii;
        const int w4   = idx & 63;
        const int jrow = (idx >> 6) % SDEP;
        const int b    = idx / (SDEP * 64);
        const int base = b * SDEP * 64;
        float4 cur = sin4[base + jrow * 64 + w4];
        float4 o;
        if (is_t0) {
            o = cur;
        } else {
            const float pu = ctlbuf[b * 3 + 0];
            const float po = ctlbuf[b * 3 + 1];
            const float nn = ctlbuf[b * 3 + 2];
            float4 up = (jrow == 0) ? d4[b * 64 + w4] : sin4[base + (jrow - 1) * 64 + w4];
            float4 dn = make_float4(0.f, 0.f, 0.f, 0.f);
            if (jrow < SDEP - 1) dn = sin4[base + (jrow + 1) * 64 + w4];
            o.x = nn * cur.x + pu * up.x + po * dn.x;
            o.y = nn * cur.y + pu * up.y + po * dn.y;
            o.z = nn * cur.z + pu * up.z + po * dn.z;
            o.w = nn * cur.w + pu * up.w + po * dn.w;
        }
        sout4[idx] = o;
    }
}

// ---------------- the persistent kernel (prep + 512 steps) ----------------
__global__ __launch_bounds__(NT) void stackrnn_persistent(
    const float* __restrict__ x,      // [S, B, IN]
    const float* __restrict__ h0,
    const float* __restrict__ W_ih,   // [4H, IS]
    const float* __restrict__ W_hh,   // [4H, H]
    const float* __restrict__ b_ih,
    const float* __restrict__ b_hh,
    const float* __restrict__ A_w,
    const float* __restrict__ A_b,
    const float* __restrict__ D_w,
    const float* __restrict__ D_b,
    float* __restrict__ outs,         // [S, B, H]
    float* __restrict__ stackn)       // [B, SDEP, SWID]
{
    extern __shared__ __align__(16) float sm[];   // [0,2*BUFSZ) A frags, [BBASE,+4*4096) B ring

    const int bid = blockIdx.x;
    const int tid = threadIdx.x;
    const int warp = tid >> 5, lane = tid & 31;
    const int wm = warp >> 2, wn = warp & 3;        // 4m x 4n warps
    const int gi_r = lane >> 2, tig = lane & 3;
    const int jt = bid & 31, mt = bid >> 5, bm0 = mt * 64;
    const int j0 = jt * 32;

    // ======== prep P1: plain tf32 weights -> g_stackB, fused bias ========
    for (int idx = bid * NT + tid; idx < 4 * HID * KTOT; idx += NB * NT) {
        int row = idx / KTOT, k = idx - row * KTOT;
        float v = (k < IS) ? W_ih[(size_t)row * IS + k]
                           : W_hh[(size_t)row * HID + (k - IS)];
        g_stackB[idx] = ftf32(v);
    }
    for (int i = bid * NT + tid; i < 4 * HID; i += NB * NT)
        g_bias[i] = b_ih[i] + b_hh[i];
    gbar();
    // ======== prep P2: tile-order swizzle -> g_Wf ========
    // idx = (jt*48+kc)*4096 + wn*1024 + g*256 + lane*8 + w ; w = ks*2+p
    // value = Wplain[row][k], row = g*HID + jt*32 + wn*8 + (lane>>2),
    // k = kc*32 + (w>>1)*8 + (lane&3) + 4*(w&1)
    for (int idx = bid * NT + tid; idx < 32 * 48 * 4096; idx += NB * NT) {
        int w    = idx & 7;
        int ln   = (idx >> 3) & 31;
        int g    = (idx >> 8) & 3;
        int wnn  = (idx >> 10) & 3;
        int kc   = (idx >> 12) % 48;
        int jtt  = idx / (48 * 4096);
        int row = g * HID + jtt * 32 + wnn * 8 + (ln >> 2);
        int k   = kc * 32 + (w >> 1) * 8 + (ln & 3) + 4 * (w & 1);
        g_Wf[idx] = g_stackB[(size_t)row * KTOT + k];
    }
    gbar();

    // A loader role: thread -> row lr (0..63), k-offset lk
    const int lr = tid >> 3;            // 0..63
    const int lk = (tid & 7) << 2;      // 0,4,...,28
    const int lb = bm0 + lr;
    // frag-scatter constants for stsA
    const int s_mt  = lr >> 4;
    const int s_gid = lr & 7;
    const int s_hi  = (lr >> 3) & 1;
    const int s_ks  = lk >> 3;
    const int s_q   = (lk >> 2) & 1;
    const int s_w   = s_hi + 2 * s_q;
    const int s_off = (s_mt * 4 + s_ks) * 132 + (s_gid * 4) * 4 + s_w;
    // B fill/read bases
    const uint32_t smem_base = smem_u32(sm);
    const uint32_t bfill_dst = smem_base + BBASE * 4 + tid * 32;    // +buf*16KB
    const float*   bsrc_base = g_Wf + (size_t)jt * 48 * 4096 + tid * 8;
    const float*   brd_base  = sm + BBASE + wn * 1024 + lane * 8;   // +buf*4096 +g*256

    for (int t = 0; t < S_LEN; t++) {
        const float* x_t    = x + (size_t)t * BATCH * IN;
        const float* h_prev = t ? outs + (size_t)(t - 1) * BATCH * HID : h0;
        float*       h_out  = outs + (size_t)t * BATCH * HID;
        const float* Sp = (t & 1) ? g_stackB : g_stackA;
        float*       So = (t & 1) ? g_stackA : g_stackB;
        const float* dprev   = g_d   + ((t + 1) & 1) * (BATCH * SWID);
        const float* ctlprev = g_ctl + ((t + 1) & 1) * (BATCH * 3);
        float*       dcur    = g_d   + (t & 1) * (BATCH * SWID);
        float*       ctlcur  = g_ctl + (t & 1) * (BATCH * 3);

        float cpu = 0.f, cpo = 0.f, cnn = 1.f;
        if (t) {
            cpu = ctlprev[lb * 3 + 0];
            cpo = ctlprev[lb * 3 + 1];
            cnn = ctlprev[lb * 3 + 2];
        }
        const float* pX = x_t + (size_t)lb * IN + lk;
        const float* pS = Sp + (size_t)lb * (SDEP * SWID) + lk - IN;   // valid kk in [IN,IS)
        const float* pD = dprev + (size_t)lb * SWID + lk - IN;
        const float* pH = h_prev + (size_t)lb * HID + lk - IS;

        auto ldgA = [&](int kc) -> float4 {
            const int kk = kc * 32 + lk;
            if (kk < IN) {
                return *(const float4*)(pX + kc * 32);
            } else if (kk < IS) {
                float4 s0 = *(const float4*)(pS + kc * 32);
                if (t == 0) return s0;
                float4 s1 = *(const float4*)(pS + SWID + kc * 32);
                float4 dv = *(const float4*)(pD + kc * 32);
                float4 v;
                v.x = cnn * s0.x + cpu * dv.x + cpo * s1.x;
                v.y = cnn * s0.y + cpu * dv.y + cpo * s1.y;
                v.z = cnn * s0.z + cpu * dv.z + cpo * s1.z;
                v.w = cnn * s0.w + cpu * dv.w + cpo * s1.w;
                return v;
            } else {
                return *(const float4*)(pH + kc * 32);
            }
        };
        auto stsA = [&](int buf, float4 v) {
            float* p = &sm[buf * BUFSZ + s_off];
            p[0]  = ftf32(v.x);
            p[4]  = ftf32(v.y);
            p[8]  = ftf32(v.z);
            p[12] = ftf32(v.w);
        };
        auto fillB = [&](int kc) {
            const uint32_t dst = bfill_dst + (kc & 3) * 16384;
            const float*   src = bsrc_base + (size_t)kc * 4096;
            cpa16(dst, src);
            cpa16(dst + 16, src + 4);
        };

        // ---- phase 1: gates GEMM, warp = 16m x (4 gates x 8j) ----
        float acc[4][4];
#pragma unroll
        for (int g = 0; g < 4; g++)
#pragma unroll
            for (int cc = 0; cc < 4; cc++) acc[g][cc] = 0.f;

        // prologue: B ring 0,1,2 in flight; A(0) stored, A(1)/A(2) in regs
        fillB(0); cpa_commit();
        fillB(1); cpa_commit();
        fillB(2); cpa_commit();
        float4 vSts = ldgA(0);
        stsA(0, vSts);
        vSts = ldgA(1);
        float4 vLdg = ldgA(2);

        for (int kc = 0; kc < 48; kc++) {
            cpa_wait<2>();
            __syncthreads();
            // B frags from smem ring
            const float4* bp = (const float4*)(brd_base + (kc & 3) * 4096);
            float4 bb[4][2];
#pragma unroll
            for (int g = 0; g < 4; g++) {
                bb[g][0] = bp[g * 64 + 0];
                bb[g][1] = bp[g * 64 + 1];
            }
            // mma over 4 ks
            const int buf = kc & 1;
#pragma unroll
            for (int ks = 0; ks < 4; ks++) {
                const float4 af = *(const float4*)&sm[buf * BUFSZ + (wm * 4 + ks) * 132 + lane * 4];
                uint32_t a[4] = {__float_as_uint(af.x), __float_as_uint(af.y),
                                 __float_as_uint(af.z), __float_as_uint(af.w)};
#pragma unroll
                for (int g = 0; g < 4; g++) {
                    float2 s;
                    if (ks == 0)      s = make_float2(bb[g][0].x, bb[g][0].y);
                    else if (ks == 1) s = make_float2(bb[g][0].z, bb[g][0].w);
                    else if (ks == 2) s = make_float2(bb[g][1].x, bb[g][1].y);
                    else              s = make_float2(bb[g][1].z, bb[g][1].w);
                    uint32_t bf[2] = {__float_as_uint(s.x), __float_as_uint(s.y)};
                    mma_tf32(acc[g], a, bf);
                }
            }
            // stage next A / B
            if (kc + 1 < 48) {
                stsA((kc + 1) & 1, vSts);
                vSts = vLdg;
                if (kc + 3 < 48) vLdg = ldgA(kc + 3);
            }
            if (kc + 3 < 48) fillB(kc + 3);
            cpa_commit();
        }

        // ---- LSTM pointwise epilogue, direct from registers ----
        {
            const int jb = j0 + wn * 8 + (tig << 1);
            const float2 B0 = *(const float2*)(g_bias + jb);
            const float2 B1 = *(const float2*)(g_bias + HID + jb);
            const float2 B2 = *(const float2*)(g_bias + 2 * HID + jb);
            const float2 B3 = *(const float2*)(g_bias + 3 * HID + jb);
#pragma unroll
            for (int cc = 0; cc < 4; cc++) {
                const int row = wm * 16 + ((cc >> 1) << 3) + gi_r;
                const int b = bm0 + row;
                const int odd = cc & 1;
                const size_t off = (size_t)b * HID + jb + odd;
                float gi = acc[0][cc] + (odd ? B0.y : B0.x);
                float gf = acc[1][cc] + (odd ? B1.y : B1.x);
                float gg = acc[2][cc] + (odd ? B2.y : B2.x);
                float go = acc[3][cc] + (odd ? B3.y : B3.x);
                float iv = 1.f / (1.f + expf(-gi));
                float fv = 1.f / (1.f + expf(-gf));
                float gv = tanhf(gg);
                float ov = 1.f / (1.f + expf(-go));
                float cn_ = fv * g_c[off] + iv * gv;
                g_c[off]  = cn_;
                h_out[off] = ov * tanhf(cn_);
            }
        }

        // ---- barrier A (split): blend overlaps the wait ----
        unsigned myg;
        bar_arrive(&myg);
        blend_range(Sp, So, dprev, ctlprev, t == 0, bid, tid);
        bar_wait(myg);

        // ---- phase 2: d = tanh(h @ D_w^T + D_b); controls softmax ----
        if (bid < 64) {
            const int bx = bid & 7, by = bid >> 3;
            const int w0 = bx * 32, bm0d = by * 32;
            const int wm2 = warp >> 2, wn2 = warp & 3;
            const int arow = tid >> 3;          // valid for tid < 256
            const int kl2  = (tid & 7) << 2;
            float acc2[4] = {0.f, 0.f, 0.f, 0.f};
            for (int kc = 0; kc < HID; kc += 32) {
                if (tid < 256) {
                    const int kk = kc + kl2;
                    {
                        float4 v = *(const float4*)(h_out + (size_t)(bm0d + arow) * HID + kk);
                        float* p = &sm[arow * 36 + kl2];
                        p[0] = ftf32(v.x); p[1] = ftf32(v.y); p[2] = ftf32(v.z); p[3] = ftf32(v.w);
                    }
                    {
                        float4 v = *(const float4*)(D_w + (size_t)(w0 + arow) * HID + kk);
                        float* p = &sm[1152 + arow * 36 + kl2];
                        p[0] = ftf32(v.x); p[1] = ftf32(v.y); p[2] = ftf32(v.z); p[3] = ftf32(v.w);
                    }
                }
                __syncthreads();
                if (warp < 8) {
#pragma unroll
                    for (int ks = 0; ks < 4; ks++) {
                        const int k0 = ks * 8;
                        uint32_t a[4], bf[2];
                        const int m0 = wm2 * 16;
                        a[0] = __float_as_uint(sm[(m0 + gi_r) * 36 + k0 + tig]);
                        a[1] = __float_as_uint(sm[(m0 + 8 + gi_r) * 36 + k0 + tig]);
                        a[2] = __float_as_uint(sm[(m0 + gi_r) * 36 + k0 + tig + 4]);
                        a[3] = __float_as_uint(sm[(m0 + 8 + gi_r) * 36 + k0 + tig + 4]);
                        const int n0 = wn2 * 8;
                        bf[0] = __float_as_uint(sm[1152 + (n0 + gi_r) * 36 + k0 + tig]);
                        bf[1] = __float_as_uint(sm[1152 + (n0 + gi_r) * 36 + k0 + tig + 4]);
                        mma_tf32(acc2, a, bf);
                    }
                }
                __syncthreads();
            }
            if (warp < 8) {
#pragma unroll
                for (int cc = 0; cc < 4; cc++) {
                    const int row = wm2 * 16 + ((cc >> 1) << 3) + gi_r;
                    const int col = wn2 * 8 + (tig << 1) + (cc & 1);
                    dcur[(size_t)(bm0d + row) * SWID + w0 + col] =
                        tanhf(acc2[cc] + D_b[w0 + col]);
                }
            }
        } else if (bid < 72) {
            const int bm0c = (bid - 64) * 32;
            for (int q = 0; q < 2; q++) {
                const int b = bm0c + warp * 2 + q;
                float s0 = 0.f, s1 = 0.f, s2 = 0.f;
                for (int k = lane; k < HID; k += 32) {
                    float hv = h_out[(size_t)b * HID + k];
                    s0 += hv * A_w[k];
                    s1 += hv * A_w[HID + k];
                    s2 += hv * A_w[2 * HID + k];
                }
#pragma unroll
                for (int o = 16; o > 0; o >>= 1) {
                    s0 += __shfl_xor_sync(0xffffffffu, s0, o);
                    s1 += __shfl_xor_sync(0xffffffffu, s1, o);
                    s2 += __shfl_xor_sync(0xffffffffu, s2, o);
                }
                if (lane == 0) {
                    s0 += A_b[0]; s1 += A_b[1]; s2 += A_b[2];
                    float mx = fmaxf(s0, fmaxf(s1, s2));
                    float e0 = expf(s0 - mx), e1 = expf(s1 - mx), e2 = expf(s2 - mx);
                    float inv = 1.f / (e0 + e1 + e2);
                    ctlcur[b * 3 + 0] = e0 * inv;
                    ctlcur[b * 3 + 1] = e1 * inv;
                    ctlcur[b * 3 + 2] = e2 * inv;
                }
            }
        }
        gbar();   // d_t / ctl_t visible for step t+1
    }

    // ---- final stack: R_512 = blend(R_511, d_511, ctl_511) -> stackn ----
    blend_range(g_stackA, stackn, g_d + BATCH * SWID, g_ctl + BATCH * 3, 0, bid, tid);
}

// ---------------- launch ----------------
extern "C" void kernel_launch(void* const* d_in, const int* in_sizes, int n_in,
                              void* d_out, int out_size)
{
    const float* x    = (const float*)d_in[0];
    const float* h0   = (const float*)d_in[1];
    const float* c0   = (const float*)d_in[2];
    const float* st0  = (const float*)d_in[3];
    const float* W_ih = (const float*)d_in[4];
    const float* W_hh = (const float*)d_in[5];
    const float* b_ih = (const float*)d_in[6];
    const float* b_hh = (const float*)d_in[7];
    const float* A_w  = (const float*)d_in[8];
    const float* A_b  = (const float*)d_in[9];
    const float* D_w  = (const float*)d_in[10];
    const float* D_b  = (const float*)d_in[11];

    float* out    = (float*)d_out;
    float* outs   = out;
    float* hn     = outs + (size_t)S_LEN * BATCH * HID;
    float* cn     = hn + (size_t)BATCH * HID;
    float* stackn = cn + (size_t)BATCH * HID;

    float *sA, *cbuf;
    cudaGetSymbolAddress((void**)&sA, g_stackA);
    cudaGetSymbolAddress((void**)&cbuf, g_c);

    cudaFuncSetAttribute(stackrnn_persistent,
                         cudaFuncAttributeMaxDynamicSharedMemorySize, DYNSM);

    cudaMemcpyAsync(cbuf, c0, sizeof(float) * BATCH * HID, cudaMemcpyDeviceToDevice);
    cudaMemcpyAsync(sA, st0, sizeof(float) * BATCH * SDEP * SWID, cudaMemcpyDeviceToDevice);

    stackrnn_persistent<<<NB, NT, DYNSM>>>(x, h0, W_ih, W_hh, b_ih, b_hh,
                                           A_w, A_b, D_w, D_b, outs, stackn);

    cudaMemcpyAsync(hn, outs + (size_t)(S_LEN - 1) * BATCH * HID,
                    sizeof(float) * BATCH * HID, cudaMemcpyDeviceToDevice);
    cudaMemcpyAsync(cn, cbuf, sizeof(float) * BATCH * HID, cudaMemcpyDeviceToDevice);
}

// round 10
// speedup vs baseline: 1.0742x; 1.0742x over previous
#include <cuda_runtime.h>
#include <cstdint>
#include <math.h>

#define S_LEN 512
#define BATCH 256
#define IN    256
#define HID   1024
#define SWID  256
#define SDEP  100
#define KTOT  1536
#define IS    (IN + SWID)     // 512
#define NB    128
#define NT    512

#define BUFSZ  4224           // A frag buffer per stage: 4 mt * 8 ks * 132
#define BBASE  (2 * BUFSZ)    // float offset of B ring
#define DYNSM  ((2 * BUFSZ + 3 * 8192) * 4)   // 132096 bytes

// ---------------- scratch (no allocations allowed) ----------------
__device__ __align__(16) float g_stackA[BATCH * SDEP * SWID];   // 26.2 MB
__device__ __align__(16) float g_stackB[BATCH * SDEP * SWID];   // 26.2 MB (also prep staging)
__device__ __align__(16) float g_Wf[32 * 48 * 4096];            // 25.2 MB tile-ordered weights
__device__ __align__(16) float g_bias[4 * HID];
__device__ __align__(16) float g_c[BATCH * HID];
__device__ __align__(16) float g_d[2 * BATCH * SWID];
__device__ float g_ctl[2 * BATCH * 3];
__device__ unsigned g_cnt;
__device__ volatile unsigned g_gen;

// ---------------- helpers ----------------
__device__ __forceinline__ float ftf32(float x) {
    float y;
    asm("cvt.rna.tf32.f32 %0, %1;" : "=f"(y) : "f"(x));
    return y;
}
__device__ __forceinline__ uint32_t smem_u32(const void* p) {
    uint32_t a;
    asm("{ .reg .u64 t; cvta.to.shared.u64 t, %1; cvt.u32.u64 %0, t; }" : "=r"(a) : "l"(p));
    return a;
}
__device__ __forceinline__ void cpa16(uint32_t dst, const void* src) {
    asm volatile("cp.async.cg.shared.global [%0], [%1], 16;" :: "r"(dst), "l"(src) : "memory");
}
__device__ __forceinline__ void cpa_commit() { asm volatile("cp.async.commit_group;" ::: "memory"); }
template <int N> __device__ __forceinline__ void cpa_wait() {
    asm volatile("cp.async.wait_group %0;" :: "n"(N) : "memory");
}

__device__ __forceinline__ void mma_tf32(float c[4], const uint32_t a[4], const uint32_t b[2]) {
    asm volatile(
        "mma.sync.aligned.m16n8k8.row.col.f32.tf32.tf32.f32 "
        "{%0,%1,%2,%3}, {%4,%5,%6,%7}, {%8,%9}, {%0,%1,%2,%3};\n"
        : "+f"(c[0]), "+f"(c[1]), "+f"(c[2]), "+f"(c[3])
        : "r"(a[0]), "r"(a[1]), "r"(a[2]), "r"(a[3]), "r"(b[0]), "r"(b[1]));
}

// ---------------- software grid barrier ----------------
__device__ __forceinline__ void bar_arrive(unsigned* myGen) {
    __syncthreads();
    if (threadIdx.x == 0) {
        unsigned my = g_gen;
        __threadfence();
        unsigned a = atomicAdd(&g_cnt, 1u);
        if (a == NB - 1) {
            g_cnt = 0;
            __threadfence();
            g_gen = my + 1;
        }
        *myGen = my;
    }
}
__device__ __forceinline__ void bar_wait(unsigned myGen) {
    if (threadIdx.x == 0) {
        while (g_gen == myGen) { }
        __threadfence();
    }
    __syncthreads();
}
__device__ __forceinline__ void gbar() {
    unsigned m;
    bar_arrive(&m);
    bar_wait(m);
}

// ---------------- stack blend ----------------
__device__ __forceinline__ void blend_range(
    const float* __restrict__ Sp, float* __restrict__ So,
    const float* __restrict__ dbuf, const float* __restrict__ ctlbuf,
    int is_t0, int bid, int tid)
{
    const float4* sin4  = (const float4*)Sp;
    float4*       sout4 = (float4*)So;
    const float4* d4    = (const float4*)dbuf;
    const int per_blk = (BATCH * SDEP * (SWID / 4)) / NB;   // 12800
    for (int ii = tid; ii < per_blk; ii += NT) {
        const int idx = bid * per_blk + ii;
        const int w4   = idx & 63;
        const int jrow = (idx >> 6) % SDEP;
        const int b    = idx / (SDEP * 64);
        const int base = b * SDEP * 64;
        float4 cur = sin4[base + jrow * 64 + w4];
        float4 o;
        if (is_t0) {
            o = cur;
        } else {
            const float pu = ctlbuf[b * 3 + 0];
            const float po = ctlbuf[b * 3 + 1];
            const float nn = ctlbuf[b * 3 + 2];
            float4 up = (jrow == 0) ? d4[b * 64 + w4] : sin4[base + (jrow - 1) * 64 + w4];
            float4 dn = make_float4(0.f, 0.f, 0.f, 0.f);
            if (jrow < SDEP - 1) dn = sin4[base + (jrow + 1) * 64 + w4];
            o.x = nn * cur.x + pu * up.x + po * dn.x;
            o.y = nn * cur.y + pu * up.y + po * dn.y;
            o.z = nn * cur.z + pu * up.z + po * dn.z;
            o.w = nn * cur.w + pu * up.w + po * dn.w;
        }
        sout4[idx] = o;
    }
}

// ---------------- the persistent kernel (prep + 512 steps) ----------------
__global__ __launch_bounds__(NT) void stackrnn_persistent(
    const float* __restrict__ x,      // [S, B, IN]
    const float* __restrict__ h0,
    const float* __restrict__ W_ih,   // [4H, IS]
    const float* __restrict__ W_hh,   // [4H, H]
    const float* __restrict__ b_ih,
    const float* __restrict__ b_hh,
    const float* __restrict__ A_w,
    const float* __restrict__ A_b,
    const float* __restrict__ D_w,
    const float* __restrict__ D_b,
    float* __restrict__ outs,         // [S, B, H]
    float* __restrict__ stackn)       // [B, SDEP, SWID]
{
    extern __shared__ __align__(16) float sm[];   // [0,2*BUFSZ) A frags, [BBASE,+3*8192) B ring

    const int bid = blockIdx.x;
    const int tid = threadIdx.x;
    const int warp = tid >> 5, lane = tid & 31;
    const int wm = warp >> 2, wn = warp & 3;        // 4m x 4n warps (phase 1)
    const int gi_r = lane >> 2, tig = lane & 3;
    const int jt = bid & 31, mt = bid >> 5, bm0 = mt * 64;
    const int j0 = jt * 32;

    // ======== prep P1: plain tf32 weights -> g_stackB, fused bias ========
    for (int idx = bid * NT + tid; idx < 4 * HID * KTOT; idx += NB * NT) {
        int row = idx / KTOT, k = idx - row * KTOT;
        float v = (k < IS) ? W_ih[(size_t)row * IS + k]
                           : W_hh[(size_t)row * HID + (k - IS)];
        g_stackB[idx] = ftf32(v);
    }
    for (int i = bid * NT + tid; i < 4 * HID; i += NB * NT)
        g_bias[i] = b_ih[i] + b_hh[i];
    gbar();
    // ======== prep P2: tile-order swizzle -> g_Wf ========
    for (int idx = bid * NT + tid; idx < 32 * 48 * 4096; idx += NB * NT) {
        int w    = idx & 7;
        int ln   = (idx >> 3) & 31;
        int g    = (idx >> 8) & 3;
        int wnn  = (idx >> 10) & 3;
        int kc   = (idx >> 12) % 48;
        int jtt  = idx / (48 * 4096);
        int row = g * HID + jtt * 32 + wnn * 8 + (ln >> 2);
        int k   = kc * 32 + (w >> 1) * 8 + (ln & 3) + 4 * (w & 1);
        g_Wf[idx] = g_stackB[(size_t)row * KTOT + k];
    }
    gbar();

    // A loader role: thread -> row lr (0..63), k-offset lk within 64-chunk halves
    const int lr = tid >> 3;            // 0..63
    const int lk = (tid & 7) << 2;      // 0,4,...,28
    const int lb = bm0 + lr;
    // frag-scatter constants (8 ks slots per stage)
    const int s_mt  = lr >> 4;
    const int s_gid = lr & 7;
    const int s_hi  = (lr >> 3) & 1;
    const int s_ks  = lk >> 3;
    const int s_q   = (lk >> 2) & 1;
    const int s_w   = s_hi + 2 * s_q;
    const int s_off = (s_mt * 8 + s_ks) * 132 + (s_gid * 4) * 4 + s_w;   // first half
    // B fill/read bases
    const uint32_t smem_base = smem_u32(sm);
    const uint32_t bfill_dst = smem_base + BBASE * 4 + tid * 64;    // 16 floats per thread
    const float*   bsrc_base = g_Wf + (size_t)jt * 48 * 4096 + tid * 16;
    const float*   brd_base  = sm + BBASE + wn * 1024 + lane * 8;

    for (int t = 0; t < S_LEN; t++) {
        const float* x_t    = x + (size_t)t * BATCH * IN;
        const float* h_prev = t ? outs + (size_t)(t - 1) * BATCH * HID : h0;
        float*       h_out  = outs + (size_t)t * BATCH * HID;
        const float* Sp = (t & 1) ? g_stackB : g_stackA;
        float*       So = (t & 1) ? g_stackA : g_stackB;
        const float* dprev   = g_d   + ((t + 1) & 1) * (BATCH * SWID);
        const float* ctlprev = g_ctl + ((t + 1) & 1) * (BATCH * 3);
        float*       dcur    = g_d   + (t & 1) * (BATCH * SWID);
        float*       ctlcur  = g_ctl + (t & 1) * (BATCH * 3);

        float cpu = 0.f, cpo = 0.f, cnn = 1.f;
        if (t) {
            cpu = ctlprev[lb * 3 + 0];
            cpo = ctlprev[lb * 3 + 1];
            cnn = ctlprev[lb * 3 + 2];
        }
        const float* pX = x_t + (size_t)lb * IN + lk;
        const float* pS = Sp + (size_t)lb * (SDEP * SWID) + lk - IN;   // valid k in [IN,IS)
        const float* pD = dprev + (size_t)lb * SWID + lk - IN;
        const float* pH = h_prev + (size_t)lb * HID + lk - IS;

        // kc64 regions: x = kc 0..3, stack = kc 4..7, h = kc 8..23 (64-aligned)
        auto ldgA = [&](int kc, float4 v[2]) {
#pragma unroll
            for (int hh = 0; hh < 2; hh++) {
                const int kk = kc * 64 + hh * 32 + lk;
                if (kk < IN) {
                    v[hh] = *(const float4*)(pX + kk - lk);
                } else if (kk < IS) {
                    float4 s0 = *(const float4*)(pS + kk - lk);
                    if (t == 0) {
                        v[hh] = s0;
                    } else {
                        float4 s1 = *(const float4*)(pS + SWID + kk - lk);
                        float4 dv = *(const float4*)(pD + kk - lk);
                        float4 q;
                        q.x = cnn * s0.x + cpu * dv.x + cpo * s1.x;
                        q.y = cnn * s0.y + cpu * dv.y + cpo * s1.y;
                        q.z = cnn * s0.z + cpu * dv.z + cpo * s1.z;
                        q.w = cnn * s0.w + cpu * dv.w + cpo * s1.w;
                        v[hh] = q;
                    }
                } else {
                    v[hh] = *(const float4*)(pH + kk - lk);
                }
            }
        };
        auto stsA = [&](int buf, const float4 v[2]) {
#pragma unroll
            for (int hh = 0; hh < 2; hh++) {
                float* p = &sm[buf * BUFSZ + s_off + hh * (4 * 132)];
                p[0]  = ftf32(v[hh].x);
                p[4]  = ftf32(v[hh].y);
                p[8]  = ftf32(v[hh].z);
                p[12] = ftf32(v[hh].w);
            }
        };
        auto fillB = [&](int kc) {
            const uint32_t dst = bfill_dst + (kc % 3) * 32768;
            const float*   src = bsrc_base + (size_t)kc * 8192;
            cpa16(dst,      src);
            cpa16(dst + 16, src + 4);
            cpa16(dst + 32, src + 8);
            cpa16(dst + 48, src + 12);
        };

        // ---- phase 1: gates GEMM, 24 iterations of K=64 ----
        float acc[4][4];
#pragma unroll
        for (int g = 0; g < 4; g++)
#pragma unroll
            for (int cc = 0; cc < 4; cc++) acc[g][cc] = 0.f;

        float4 vA[2];
        fillB(0); cpa_commit();
        fillB(1); cpa_commit();
        ldgA(0, vA);
        stsA(0, vA);

        for (int kc = 0; kc < 24; kc++) {
            cpa_wait<1>();
            __syncthreads();
            const float* bring = brd_base + (kc % 3) * 8192;
            if (kc + 1 < 24) ldgA(kc + 1, vA);
#pragma unroll
            for (int hh = 0; hh < 2; hh++) {
                // B frags for this 32-k half
                const float4* bp = (const float4*)(bring + hh * 4096);
                float4 bb[4][2];
#pragma unroll
                for (int g = 0; g < 4; g++) {
                    bb[g][0] = bp[g * 64 + 0];
                    bb[g][1] = bp[g * 64 + 1];
                }
#pragma unroll
                for (int ks = 0; ks < 4; ks++) {
                    const float4 af = *(const float4*)
                        &sm[(kc & 1) * BUFSZ + (wm * 8 + hh * 4 + ks) * 132 + lane * 4];
                    uint32_t a[4] = {__float_as_uint(af.x), __float_as_uint(af.y),
                                     __float_as_uint(af.z), __float_as_uint(af.w)};
#pragma unroll
                    for (int g = 0; g < 4; g++) {
                        float2 s;
                        if (ks == 0)      s = make_float2(bb[g][0].x, bb[g][0].y);
                        else if (ks == 1) s = make_float2(bb[g][0].z, bb[g][0].w);
                        else if (ks == 2) s = make_float2(bb[g][1].x, bb[g][1].y);
                        else              s = make_float2(bb[g][1].z, bb[g][1].w);
                        uint32_t bf[2] = {__float_as_uint(s.x), __float_as_uint(s.y)};
                        mma_tf32(acc[g], a, bf);
                    }
                }
            }
            if (kc + 1 < 24) stsA((kc + 1) & 1, vA);
            if (kc + 2 < 24) fillB(kc + 2);
            cpa_commit();
        }

        // ---- LSTM pointwise epilogue, direct from registers ----
        {
            const int jb = j0 + wn * 8 + (tig << 1);
            const float2 B0 = *(const float2*)(g_bias + jb);
            const float2 B1 = *(const float2*)(g_bias + HID + jb);
            const float2 B2 = *(const float2*)(g_bias + 2 * HID + jb);
            const float2 B3 = *(const float2*)(g_bias + 3 * HID + jb);
#pragma unroll
            for (int cc = 0; cc < 4; cc++) {
                const int row = wm * 16 + ((cc >> 1) << 3) + gi_r;
                const int b = bm0 + row;
                const int odd = cc & 1;
                const size_t off = (size_t)b * HID + jb + odd;
                float gi = acc[0][cc] + (odd ? B0.y : B0.x);
                float gf = acc[1][cc] + (odd ? B1.y : B1.x);
                float gg = acc[2][cc] + (odd ? B2.y : B2.x);
                float go = acc[3][cc] + (odd ? B3.y : B3.x);
                float iv = 1.f / (1.f + expf(-gi));
                float fv = 1.f / (1.f + expf(-gf));
                float gv = tanhf(gg);
                float ov = 1.f / (1.f + expf(-go));
                float cn_ = fv * g_c[off] + iv * gv;
                g_c[off]  = cn_;
                h_out[off] = ov * tanhf(cn_);
            }
        }

        // ---- barrier A (split): blend overlaps the wait ----
        unsigned myg;
        bar_arrive(&myg);
        blend_range(Sp, So, dprev, ctlprev, t == 0, bid, tid);
        bar_wait(myg);

        // ---- phase 2: d = tanh(h @ D_w^T + D_b); controls softmax ----
        if (bid < 64) {
            // tile: 32 batch rows x 32 w cols; K chunks of 256
            const int w0 = (bid & 7) * 32, bm0d = (bid >> 3) * 32;
            const int mi = warp >> 3;            // 0..1
            const int ni = (warp >> 1) & 3;      // 0..3
            const int kh = warp & 1;             // 0..1 (k-split)
            const int HS = 260;                  // padded row stride
            const int BW = 32 * HS;              // 8320: D_w region offset
            const int RED = 2 * BW;              // 16640: reduction region
            const int lrow = tid >> 4;           // 0..31
            const int lcol = (tid & 15) * 4;     // float4 col base
            float acc2[4] = {0.f, 0.f, 0.f, 0.f};
            for (int ch = 0; ch < 4; ch++) {
                __syncthreads();
#pragma unroll
                for (int i = 0; i < 4; i++) {
                    const int col = lcol + i * 64;
                    float4 hv = *(const float4*)
                        (h_out + (size_t)(bm0d + lrow) * HID + ch * 256 + col);
                    float* p = &sm[lrow * HS + col];
                    p[0] = ftf32(hv.x); p[1] = ftf32(hv.y);
                    p[2] = ftf32(hv.z); p[3] = ftf32(hv.w);
                    float4 wv = *(const float4*)
                        (D_w + (size_t)(w0 + lrow) * HID + ch * 256 + col);
                    float* q = &sm[BW + lrow * HS + col];
                    q[0] = ftf32(wv.x); q[1] = ftf32(wv.y);
                    q[2] = ftf32(wv.z); q[3] = ftf32(wv.w);
                }
                __syncthreads();
#pragma unroll
                for (int ks = 0; ks < 16; ks++) {
                    const int k0 = (kh * 16 + ks) * 8;
                    uint32_t a[4], bf[2];
                    const int m0 = mi * 16;
                    a[0] = __float_as_uint(sm[(m0 + gi_r) * HS + k0 + tig]);
                    a[1] = __float_as_uint(sm[(m0 + 8 + gi_r) * HS + k0 + tig]);
                    a[2] = __float_as_uint(sm[(m0 + gi_r) * HS + k0 + tig + 4]);
                    a[3] = __float_as_uint(sm[(m0 + 8 + gi_r) * HS + k0 + tig + 4]);
                    const int n0 = ni * 8;
                    bf[0] = __float_as_uint(sm[BW + (n0 + gi_r) * HS + k0 + tig]);
                    bf[1] = __float_as_uint(sm[BW + (n0 + gi_r) * HS + k0 + tig + 4]);
                    mma_tf32(acc2, a, bf);
                }
            }
            // k-split reduction: kh=1 stores, kh=0 adds
            __syncthreads();
            if (kh == 1) {
                float* p = &sm[RED + ((mi * 4 + ni) * 32 + lane) * 4];
                p[0] = acc2[0]; p[1] = acc2[1]; p[2] = acc2[2]; p[3] = acc2[3];
            }
            __syncthreads();
            if (kh == 0) {
                const float* p = &sm[RED + ((mi * 4 + ni) * 32 + lane) * 4];
#pragma unroll
                for (int cc = 0; cc < 4; cc++) {
                    const int row = mi * 16 + ((cc >> 1) << 3) + gi_r;
                    const int col = ni * 8 + (tig << 1) + (cc & 1);
                    dcur[(size_t)(bm0d + row) * SWID + w0 + col] =
                        tanhf(acc2[cc] + p[cc] + D_b[w0 + col]);
                }
            }
        } else if (bid < 72) {
            const int bm0c = (bid - 64) * 32;
            for (int q = 0; q < 2; q++) {
                const int b = bm0c + warp * 2 + q;
                float s0 = 0.f, s1 = 0.f, s2 = 0.f;
                for (int k = lane; k < HID; k += 32) {
                    float hv = h_out[(size_t)b * HID + k];
                    s0 += hv * A_w[k];
                    s1 += hv * A_w[HID + k];
                    s2 += hv * A_w[2 * HID + k];
                }
#pragma unroll
                for (int o = 16; o > 0; o >>= 1) {
                    s0 += __shfl_xor_sync(0xffffffffu, s0, o);
                    s1 += __shfl_xor_sync(0xffffffffu, s1, o);
                    s2 += __shfl_xor_sync(0xffffffffu, s2, o);
                }
                if (lane == 0) {
                    s0 += A_b[0]; s1 += A_b[1]; s2 += A_b[2];
                    float mx = fmaxf(s0, fmaxf(s1, s2));
                    float e0 = expf(s0 - mx), e1 = expf(s1 - mx), e2 = expf(s2 - mx);
                    float inv = 1.f / (e0 + e1 + e2);
                    ctlcur[b * 3 + 0] = e0 * inv;
                    ctlcur[b * 3 + 1] = e1 * inv;
                    ctlcur[b * 3 + 2] = e2 * inv;
                }
            }
        }
        gbar();   // d_t / ctl_t visible for step t+1
    }

    // ---- final stack: R_512 = blend(R_511, d_511, ctl_511) -> stackn ----
    blend_range(g_stackA, stackn, g_d + BATCH * SWID, g_ctl + BATCH * 3, 0, bid, tid);
}

// ---------------- launch ----------------
extern "C" void kernel_launch(void* const* d_in, const int* in_sizes, int n_in,
                              void* d_out, int out_size)
{
    const float* x    = (const float*)d_in[0];
    const float* h0   = (const float*)d_in[1];
    const float* c0   = (const float*)d_in[2];
    const float* st0  = (const float*)d_in[3];
    const float* W_ih = (const float*)d_in[4];
    const float* W_hh = (const float*)d_in[5];
    const float* b_ih = (const float*)d_in[6];
    const float* b_hh = (const float*)d_in[7];
    const float* A_w  = (const float*)d_in[8];
    const float* A_b  = (const float*)d_in[9];
    const float* D_w  = (const float*)d_in[10];
    const float* D_b  = (const float*)d_in[11];

    float* out    = (float*)d_out;
    float* outs   = out;
    float* hn     = outs + (size_t)S_LEN * BATCH * HID;
    float* cn     = hn + (size_t)BATCH * HID;
    float* stackn = cn + (size_t)BATCH * HID;

    float *sA, *cbuf;
    cudaGetSymbolAddress((void**)&sA, g_stackA);
    cudaGetSymbolAddress((void**)&cbuf, g_c);

    cudaFuncSetAttribute(stackrnn_persistent,
                         cudaFuncAttributeMaxDynamicSharedMemorySize, DYNSM);

    cudaMemcpyAsync(cbuf, c0, sizeof(float) * BATCH * HID, cudaMemcpyDeviceToDevice);
    cudaMemcpyAsync(sA, st0, sizeof(float) * BATCH * SDEP * SWID, cudaMemcpyDeviceToDevice);

    stackrnn_persistent<<<NB, NT, DYNSM>>>(x, h0, W_ih, W_hh, b_ih, b_hh,
                                           A_w, A_b, D_w, D_b, outs, stackn);

    cudaMemcpyAsync(hn, outs + (size_t)(S_LEN - 1) * BATCH * HID,
                    sizeof(float) * BATCH * HID, cudaMemcpyDeviceToDevice);
    cudaMemcpyAsync(cn, cbuf, sizeof(float) * BATCH * HID, cudaMemcpyDeviceToDevice);
}